// round 3
// baseline (speedup 1.0000x reference)
#include <cuda_runtime.h>
#include <cstdint>

// LocalWindowAttention3D: mma.sync tf32 (3x split) GEMMs + SIMT attention.
// One CTA per (batch, window). 256 threads, ~206KB smem, 1 CTA/SM.
// NOTE: tcgen05 is unusable here (harness builds through compute_103 PTX,
// which rejects arch-suffixed features) -> family-portable HMMA path.

namespace {
constexpr int CDIM = 128;
constexpr int SDIM = 110592;      // 48^3
constexpr int NWIN = 1728;        // 12^3
constexpr int QP   = 68;          // qkv smem row pitch (floats)
// smem byte offsets
constexpr int O_QKV = 0;                       // 384 x 68 fp32 = 104448
constexpr int O_A   = 104448;                  // 64 x 132 fp32 weight chunk (34176B incl pad)
                                               //   aliased in attention: sc(64x65)+psum(256)+pT(64x64)
constexpr int O_BPH = 104448 + 34176;          // 138624: B tile hi (64 x 132 fp32)
constexpr int O_BPL = 138624 + 33792;          // 172416: B tile lo (64 x 132 fp32)
constexpr int SMEM_BYTES = 172416 + 33792;     // 206208
}

__device__ __forceinline__ uint32_t f2tf(float v) {
    uint32_t u; asm("cvt.rna.tf32.f32 %0, %1;" : "=r"(u) : "f"(v)); return u;
}
__device__ __forceinline__ void tf32_split(float v, uint32_t& hi, uint32_t& lo) {
    hi = f2tf(v);
    lo = f2tf(v - __uint_as_float(hi));
}
__device__ __forceinline__ void mma_tf32(float* d, uint32_t a0, uint32_t a1, uint32_t a2,
                                         uint32_t a3, uint32_t b0, uint32_t b1) {
    asm volatile(
        "mma.sync.aligned.m16n8k8.row.col.f32.tf32.tf32.f32 "
        "{%0,%1,%2,%3}, {%4,%5,%6,%7}, {%8,%9}, {%0,%1,%2,%3};"
        : "+f"(d[0]), "+f"(d[1]), "+f"(d[2]), "+f"(d[3])
        : "r"(a0), "r"(a1), "r"(a2), "r"(a3), "r"(b0), "r"(b1));
}

// Pair-packed B-tile scalar offset for (token t, channel c):
//   row pitch 132 floats; within row: kstep(c>>3)*8 + (c&3)*2 + ((c>>2)&1)
// so a float2 at [t*132 + k0 + t4*2] yields channels (k0+t4, k0+t4+4).
__device__ __forceinline__ int bp_off(int t, int c) {
    return t * 132 + (c >> 3) * 8 + (c & 3) * 2 + ((c >> 2) & 1);
}

// One 64(e) x 64(t) x 128(c) GEMM chunk: stage W rows in As (fp32), 3xTF32 mma
// against the pre-split B tile. Warp wid handles rows (wid>>1)*16, cols (wid&1)*32.
__device__ __noinline__ void gemm_chunk(const float* __restrict__ Wg, char* smc,
                                        float (&d)[4][4], int tid, int wid, int lane)
{
    float* As = reinterpret_cast<float*>(smc + O_A);
    const float* bph = reinterpret_cast<const float*>(smc + O_BPH);
    const float* bpl = reinterpret_cast<const float*>(smc + O_BPL);

    __syncthreads();   // previous users of As / B tile done
    #pragma unroll
    for (int j = 0; j < 8; ++j) {
        const int idx = tid + j * 256;
        const int r = idx >> 5, c4 = (idx & 31) * 4;
        *reinterpret_cast<float4*>(As + r * 132 + c4) =
            __ldg(reinterpret_cast<const float4*>(Wg + r * 128 + c4));
    }
    __syncthreads();

    const int g  = lane >> 2;
    const int t4 = lane & 3;
    const int nb = (wid & 1) * 32;
    const float* ar0 = As + ((wid >> 1) * 16 + g) * 132 + t4;
    const float* ar1 = ar0 + 8 * 132;

    #pragma unroll
    for (int nt = 0; nt < 4; ++nt)
        #pragma unroll
        for (int j = 0; j < 4; ++j) d[nt][j] = 0.f;

    #pragma unroll
    for (int ks = 0; ks < 16; ++ks) {
        const int k0 = ks * 8;
        uint32_t ah[4], al[4];
        tf32_split(ar0[k0],     ah[0], al[0]);
        tf32_split(ar1[k0],     ah[1], al[1]);
        tf32_split(ar0[k0 + 4], ah[2], al[2]);
        tf32_split(ar1[k0 + 4], ah[3], al[3]);
        #pragma unroll
        for (int nt = 0; nt < 4; ++nt) {
            const int t = nb + nt * 8 + g;
            const float2 bh = *reinterpret_cast<const float2*>(bph + t * 132 + k0 + t4 * 2);
            const float2 bl = *reinterpret_cast<const float2*>(bpl + t * 132 + k0 + t4 * 2);
            const uint32_t bh0 = __float_as_uint(bh.x), bh1 = __float_as_uint(bh.y);
            const uint32_t bl0 = __float_as_uint(bl.x), bl1 = __float_as_uint(bl.y);
            mma_tf32(d[nt], ah[0], ah[1], ah[2], ah[3], bh0, bh1);
            mma_tf32(d[nt], ah[0], ah[1], ah[2], ah[3], bl0, bl1);
            mma_tf32(d[nt], al[0], al[1], al[2], al[3], bh0, bh1);
        }
    }
}

__global__ __launch_bounds__(256, 1)
void lwa3d_mma(const float* __restrict__ x, const float* __restrict__ Wqkv,
               const float* __restrict__ Wout, const float* __restrict__ bout,
               float* __restrict__ out)
{
    extern __shared__ char smc[];
    float* qkv = reinterpret_cast<float*>(smc + O_QKV);
    float* bph = reinterpret_cast<float*>(smc + O_BPH);
    float* bpl = reinterpret_cast<float*>(smc + O_BPL);
    float* sc   = reinterpret_cast<float*>(smc + O_A);          // 64 x 65
    float* psum = sc + 64 * 65;                                 // 4 x 64
    float* pT   = reinterpret_cast<float*>(smc + O_A + 17664);  // 64 x 64

    const int tid  = threadIdx.x;
    const int wid  = tid >> 5;
    const int lane = tid & 31;
    const int n = blockIdx.x;
    const int b = blockIdx.y;

    // ---------- gather x window, split directly into tf32 hi/lo B tile ----------
    {
        const int ndi = n / 144, nhi = (n / 12) % 12, nwi = n % 12;
        const float* xb = x + (size_t)b * CDIM * SDIM;
        const int sbase = ((ndi * 4) * 48 + nhi * 4) * 48 + nwi * 4;
        for (int i = tid; i < CDIM * 16; i += 256) {
            const int c = i >> 4;
            const int g = i & 15;
            const int s0 = sbase + ((g >> 2) * 48 + (g & 3)) * 48;
            const float4 v = *reinterpret_cast<const float4*>(xb + (size_t)c * SDIM + s0);
            const float vv[4] = {v.x, v.y, v.z, v.w};
            #pragma unroll
            for (int j = 0; j < 4; ++j) {
                uint32_t hi, lo;
                tf32_split(vv[j], hi, lo);
                const int off = bp_off(g * 4 + j, c);
                bph[off] = __uint_as_float(hi);
                bpl[off] = __uint_as_float(lo);
            }
        }
    }

    // ---------- QKV = Wqkv @ x : 6 chunks of 64 output rows ----------
    {
        const int g = lane >> 2, t4 = lane & 3;
        const int rb = (wid >> 1) * 16 + g, nb = (wid & 1) * 32;
        for (int ch = 0; ch < 6; ++ch) {
            float d[4][4];
            gemm_chunk(Wqkv + ch * 64 * CDIM, smc, d, tid, wid, lane);
            float* q0 = qkv + (ch * 64 + rb) * QP + nb + t4 * 2;
            float* q1 = q0 + 8 * QP;
            #pragma unroll
            for (int nt = 0; nt < 4; ++nt) {
                *reinterpret_cast<float2*>(q0 + nt * 8) = make_float2(d[nt][0], d[nt][1]);
                *reinterpret_cast<float2*>(q1 + nt * 8) = make_float2(d[nt][2], d[nt][3]);
            }
        }
    }
    __syncthreads();   // qkv visible; As reads done (sc may be written now)

    // ---------- SIMT windowed attention ----------
    const float scale = 0.08838834764831845f;   // 128^-0.5
    const int q_   = tid & 63;
    const int part = tid >> 6;
    const int qg   = tid & 15;
    const int kg   = tid >> 4;

    for (int h = 0; h < 8; ++h) {
        const float* qh = qkv + (h * 16) * QP;
        const float* kh = qkv + (128 + h * 16) * QP;
        const float* vh = qkv + (256 + h * 16) * QP;

        float s4[4][4];
        #pragma unroll
        for (int a2 = 0; a2 < 4; ++a2)
            #pragma unroll
            for (int b2 = 0; b2 < 4; ++b2) s4[a2][b2] = 0.f;

        #pragma unroll
        for (int e = 0; e < 16; ++e) {
            const float4 qv = *reinterpret_cast<const float4*>(qh + e * QP + qg * 4);
            const float4 kv = *reinterpret_cast<const float4*>(kh + e * QP + kg * 4);
            const float qa[4] = {qv.x, qv.y, qv.z, qv.w};
            const float ka[4] = {kv.x, kv.y, kv.z, kv.w};
            #pragma unroll
            for (int a2 = 0; a2 < 4; ++a2)
                #pragma unroll
                for (int b2 = 0; b2 < 4; ++b2)
                    s4[a2][b2] = fmaf(qa[a2], ka[b2], s4[a2][b2]);
        }
        #pragma unroll
        for (int a2 = 0; a2 < 4; ++a2)
            #pragma unroll
            for (int b2 = 0; b2 < 4; ++b2)
                sc[(qg * 4 + a2) * 65 + kg * 4 + b2] = s4[a2][b2];
        __syncthreads();

        float lsum = 0.f;
        #pragma unroll
        for (int k = 0; k < 16; ++k)
            lsum += __expf(sc[q_ * 65 + part * 16 + k] * scale);
        psum[part * 64 + q_] = lsum;
        __syncthreads();
        const float rinv = 1.f / (psum[q_] + psum[64 + q_] + psum[128 + q_] + psum[192 + q_]);
        #pragma unroll
        for (int k = 0; k < 16; ++k) {
            const int kk = part * 16 + k;
            pT[kk * 64 + q_] = __expf(sc[q_ * 65 + kk] * scale) * rinv;
        }
        __syncthreads();

        float oacc[4] = {0.f, 0.f, 0.f, 0.f};
        #pragma unroll 4
        for (int k4 = 0; k4 < 16; ++k4) {
            const float p0 = pT[(k4 * 4 + 0) * 64 + q_];
            const float p1 = pT[(k4 * 4 + 1) * 64 + q_];
            const float p2 = pT[(k4 * 4 + 2) * 64 + q_];
            const float p3 = pT[(k4 * 4 + 3) * 64 + q_];
            #pragma unroll
            for (int j = 0; j < 4; ++j) {
                const float4 vv = *reinterpret_cast<const float4*>(vh + (part * 4 + j) * QP + k4 * 4);
                oacc[j] = fmaf(p0, vv.x, oacc[j]);
                oacc[j] = fmaf(p1, vv.y, oacc[j]);
                oacc[j] = fmaf(p2, vv.z, oacc[j]);
                oacc[j] = fmaf(p3, vv.w, oacc[j]);
            }
        }
        __syncthreads();   // sc/pT reads done before next head rewrites

        // store attention-out directly in split B-tile format (t=q_, c=h*16+part*4+j)
        #pragma unroll
        for (int j = 0; j < 4; ++j) {
            const int c = h * 16 + part * 4 + j;
            uint32_t hi, lo;
            tf32_split(oacc[j], hi, lo);
            const int off = bp_off(q_, c);
            bph[off] = __uint_as_float(hi);
            bpl[off] = __uint_as_float(lo);
        }
    }

    // ---------- out = Wout @ ao + bout : 2 chunks, write straight to GMEM ----------
    {
        const int g = lane >> 2, t4 = lane & 3;
        const int rb = (wid >> 1) * 16 + g, nb = (wid & 1) * 32;
        for (int ch = 0; ch < 2; ++ch) {
            float d[4][4];
            gemm_chunk(Wout + ch * 64 * CDIM, smc, d, tid, wid, lane);
            const int e0 = ch * 64 + rb;
            const float bb0 = __ldg(bout + e0);
            const float bb1 = __ldg(bout + e0 + 8);
            float* o0 = out + (size_t)b * CDIM * SDIM + (size_t)e0 * SDIM + n * 64 + nb + t4 * 2;
            float* o1 = o0 + (size_t)8 * SDIM;
            #pragma unroll
            for (int nt = 0; nt < 4; ++nt) {
                *reinterpret_cast<float2*>(o0 + nt * 8) =
                    make_float2(d[nt][0] + bb0, d[nt][1] + bb0);
                *reinterpret_cast<float2*>(o1 + nt * 8) =
                    make_float2(d[nt][2] + bb1, d[nt][3] + bb1);
            }
        }
    }
}

extern "C" void kernel_launch(void* const* d_in, const int* in_sizes, int n_in,
                              void* d_out, int out_size)
{
    (void)in_sizes; (void)n_in; (void)out_size;
    const float* x    = (const float*)d_in[0];
    const float* Wqkv = (const float*)d_in[1];
    const float* Wout = (const float*)d_in[2];
    const float* bout = (const float*)d_in[3];
    float* out = (float*)d_out;

    cudaFuncSetAttribute(lwa3d_mma, cudaFuncAttributeMaxDynamicSharedMemorySize, SMEM_BYTES);
    dim3 grid(NWIN, 2);
    lwa3d_mma<<<grid, 256, SMEM_BYTES>>>(x, Wqkv, Wout, bout, out);
}

// round 4
// speedup vs baseline: 2.4572x; 2.4572x over previous
#include <cuda_runtime.h>
#include <cstdint>

// LocalWindowAttention3D: inline mma.sync tf32 (3x split) GEMMs + SIMT attention.
// One CTA per (batch, window). 256 threads, ~202KB smem, 1 CTA/SM.
// Weights pre-split to tf32 hi/lo in MMA-fragment order by a prep kernel.

namespace {
constexpr int CDIM = 128;
constexpr int SDIM = 110592;      // 48^3
constexpr int NWIN = 1728;        // 12^3
constexpr int QP   = 68;          // qkv smem row pitch (floats)
constexpr int XP   = 72;          // xs smem row pitch (floats) -> conflict-free frag build
// smem byte offsets
constexpr int O_QKV = 0;                    // 384*68*4 = 104448
constexpr int O_XS  = 104448;               // 128*72*4 = 36864 (aliased by sc/psum/pT)
constexpr int O_BH  = 104448 + 36864;       // 141312: B frags hi, 8*16*32 float2 = 32KB
constexpr int O_BL  = 141312 + 32768;       // 174080: B frags lo, 32KB
constexpr int SMEM_BYTES = 174080 + 32768;  // 206848
}

// Weight fragment images: [ch(8)][wrb(4)][ks(16)][lane(32)] float4
// ch 0..5 = Wqkv rows ch*64..; ch 6..7 = Wout rows (ch-6)*64..
__device__ float4 gAh[8 * 4 * 16 * 32];
__device__ float4 gAl[8 * 4 * 16 * 32];

__device__ __forceinline__ uint32_t f2tf(float v) {
    uint32_t u; asm("cvt.rna.tf32.f32 %0, %1;" : "=r"(u) : "f"(v)); return u;
}
__device__ __forceinline__ void tf32_split(float v, uint32_t& hi, uint32_t& lo) {
    hi = f2tf(v);
    lo = f2tf(v - __uint_as_float(hi));
}
__device__ __forceinline__ void mma_tf32(float* d, uint32_t a0, uint32_t a1, uint32_t a2,
                                         uint32_t a3, uint32_t b0, uint32_t b1) {
    asm volatile(
        "mma.sync.aligned.m16n8k8.row.col.f32.tf32.tf32.f32 "
        "{%0,%1,%2,%3}, {%4,%5,%6,%7}, {%8,%9}, {%0,%1,%2,%3};"
        : "+f"(d[0]), "+f"(d[1]), "+f"(d[2]), "+f"(d[3])
        : "r"(a0), "r"(a1), "r"(a2), "r"(a3), "r"(b0), "r"(b1));
}

__global__ void prep_weights(const float* __restrict__ Wqkv, const float* __restrict__ Wout) {
    const int idx = blockIdx.x * 256 + threadIdx.x;     // 16384 frags
    const int lane = idx & 31;
    const int ks   = (idx >> 5) & 15;
    const int wrb  = (idx >> 9) & 3;
    const int ch   = idx >> 11;
    const int g = lane >> 2, t4 = lane & 3;
    const int e0 = ch * 64 + wrb * 16 + g;
    const int c0 = ks * 8 + t4;
    const float* W = (ch < 6) ? (Wqkv + (size_t)e0 * CDIM) : (Wout + (size_t)(e0 - 384) * CDIM);
    const float a[4] = {W[c0], W[8 * CDIM + c0], W[c0 + 4], W[8 * CDIM + c0 + 4]};
    float4 h, l;
    uint32_t hu, lu;
    tf32_split(a[0], hu, lu); h.x = __uint_as_float(hu); l.x = __uint_as_float(lu);
    tf32_split(a[1], hu, lu); h.y = __uint_as_float(hu); l.y = __uint_as_float(lu);
    tf32_split(a[2], hu, lu); h.z = __uint_as_float(hu); l.z = __uint_as_float(lu);
    tf32_split(a[3], hu, lu); h.w = __uint_as_float(hu); l.w = __uint_as_float(lu);
    gAh[idx] = h;
    gAl[idx] = l;
}

// One 64(e) x 64(t) x 128(c) GEMM chunk, fully inlined, register accumulators.
__device__ __forceinline__ void gemm_chunk(int ch, int wrb, int nhalf, int lane,
                                           const float2* __restrict__ bh2,
                                           const float2* __restrict__ bl2,
                                           float (&d)[4][4])
{
    const float4* pah = gAh + ((ch * 4 + wrb) * 16) * 32 + lane;
    const float4* pal = gAl + ((ch * 4 + wrb) * 16) * 32 + lane;
    #pragma unroll
    for (int nt = 0; nt < 4; ++nt)
        #pragma unroll
        for (int j = 0; j < 4; ++j) d[nt][j] = 0.f;

    #pragma unroll
    for (int ks = 0; ks < 16; ++ks) {
        const float4 ah = __ldg(pah + ks * 32);
        const float4 al = __ldg(pal + ks * 32);
        const uint32_t ah0 = __float_as_uint(ah.x), ah1 = __float_as_uint(ah.y);
        const uint32_t ah2 = __float_as_uint(ah.z), ah3 = __float_as_uint(ah.w);
        const uint32_t al0 = __float_as_uint(al.x), al1 = __float_as_uint(al.y);
        const uint32_t al2 = __float_as_uint(al.z), al3 = __float_as_uint(al.w);
        #pragma unroll
        for (int nt = 0; nt < 4; ++nt) {
            const int ci = ((nhalf * 4 + nt) * 16 + ks) * 32 + lane;
            const float2 vbh = bh2[ci];
            const float2 vbl = bl2[ci];
            const uint32_t bh0 = __float_as_uint(vbh.x), bh1 = __float_as_uint(vbh.y);
            const uint32_t bl0 = __float_as_uint(vbl.x), bl1 = __float_as_uint(vbl.y);
            mma_tf32(d[nt], ah0, ah1, ah2, ah3, bh0, bh1);
            mma_tf32(d[nt], ah0, ah1, ah2, ah3, bl0, bl1);
            mma_tf32(d[nt], al0, al1, al2, al3, bh0, bh1);
        }
    }
}

__global__ __launch_bounds__(256, 1)
void lwa3d_mma(const float* __restrict__ x, const float* __restrict__ bout,
               float* __restrict__ out)
{
    extern __shared__ char smc[];
    float* qkv = reinterpret_cast<float*>(smc + O_QKV);
    float* xs  = reinterpret_cast<float*>(smc + O_XS);
    float* sc   = xs;                 // 64 x 65 (alias, xs dead after frag build)
    float* psum = sc + 64 * 65;       // 4 x 64
    float* pT   = psum + 256;         // 64 x 64
    float2* bh2 = reinterpret_cast<float2*>(smc + O_BH);
    float2* bl2 = reinterpret_cast<float2*>(smc + O_BL);

    const int tid  = threadIdx.x;
    const int wid  = tid >> 5;
    const int lane = tid & 31;
    const int g    = lane >> 2;
    const int t4   = lane & 3;
    const int wrb  = wid >> 1;
    const int nhalf = wid & 1;
    const int n = blockIdx.x;
    const int b = blockIdx.y;

    // ---------- gather x window into xs [128c][64t] ----------
    {
        const int ndi = n / 144, nhi = (n / 12) % 12, nwi = n % 12;
        const float* xb = x + (size_t)b * CDIM * SDIM;
        const int sbase = ((ndi * 4) * 48 + nhi * 4) * 48 + nwi * 4;
        for (int i = tid; i < CDIM * 16; i += 256) {
            const int c = i >> 4;
            const int gg = i & 15;
            const int s0 = sbase + ((gg >> 2) * 48 + (gg & 3)) * 48;
            *reinterpret_cast<float4*>(xs + c * XP + gg * 4) =
                *reinterpret_cast<const float4*>(xb + (size_t)c * SDIM + s0);
        }
    }
    __syncthreads();

    // ---------- build tf32 hi/lo B fragments from xs ----------
    // cell = [tb(8)][ks(16)][lane(32)]: float2 = {B[ks*8+t4][t], B[ks*8+t4+4][t]}, t = tb*8+g
    for (int cell = tid; cell < 4096; cell += 256) {
        const int l2 = cell & 31;
        const int ks = (cell >> 5) & 15;
        const int tb = cell >> 9;
        const int t  = tb * 8 + (l2 >> 2);
        const int c0 = ks * 8 + (l2 & 3);
        uint32_t h0, l0, h1, l1;
        tf32_split(xs[c0 * XP + t], h0, l0);
        tf32_split(xs[(c0 + 4) * XP + t], h1, l1);
        bh2[cell] = make_float2(__uint_as_float(h0), __uint_as_float(h1));
        bl2[cell] = make_float2(__uint_as_float(l0), __uint_as_float(l1));
    }
    __syncthreads();

    // ---------- QKV = Wqkv @ x : 6 chunks of 64 rows, no syncs ----------
    #pragma unroll 1
    for (int ch = 0; ch < 6; ++ch) {
        float d[4][4];
        gemm_chunk(ch, wrb, nhalf, lane, bh2, bl2, d);
        float* q0 = qkv + (ch * 64 + wrb * 16 + g) * QP + nhalf * 32 + t4 * 2;
        float* q1 = q0 + 8 * QP;
        #pragma unroll
        for (int nt = 0; nt < 4; ++nt) {
            *reinterpret_cast<float2*>(q0 + nt * 8) = make_float2(d[nt][0], d[nt][1]);
            *reinterpret_cast<float2*>(q1 + nt * 8) = make_float2(d[nt][2], d[nt][3]);
        }
    }
    __syncthreads();

    // ---------- SIMT windowed attention ----------
    const float scale = 0.08838834764831845f;   // 128^-0.5
    const int q_   = tid & 63;
    const int part = tid >> 6;
    const int qg   = tid & 15;
    const int kg   = tid >> 4;

    for (int h = 0; h < 8; ++h) {
        const float* qh = qkv + (h * 16) * QP;
        const float* kh = qkv + (128 + h * 16) * QP;
        const float* vh = qkv + (256 + h * 16) * QP;

        float s4[4][4];
        #pragma unroll
        for (int a2 = 0; a2 < 4; ++a2)
            #pragma unroll
            for (int b2 = 0; b2 < 4; ++b2) s4[a2][b2] = 0.f;

        #pragma unroll
        for (int e = 0; e < 16; ++e) {
            const float4 qv = *reinterpret_cast<const float4*>(qh + e * QP + qg * 4);
            const float4 kv = *reinterpret_cast<const float4*>(kh + e * QP + kg * 4);
            const float qa[4] = {qv.x, qv.y, qv.z, qv.w};
            const float ka[4] = {kv.x, kv.y, kv.z, kv.w};
            #pragma unroll
            for (int a2 = 0; a2 < 4; ++a2)
                #pragma unroll
                for (int b2 = 0; b2 < 4; ++b2)
                    s4[a2][b2] = fmaf(qa[a2], ka[b2], s4[a2][b2]);
        }
        #pragma unroll
        for (int a2 = 0; a2 < 4; ++a2)
            #pragma unroll
            for (int b2 = 0; b2 < 4; ++b2)
                sc[(qg * 4 + a2) * 65 + kg * 4 + b2] = s4[a2][b2];
        __syncthreads();

        float lsum = 0.f;
        #pragma unroll
        for (int k = 0; k < 16; ++k)
            lsum += __expf(sc[q_ * 65 + part * 16 + k] * scale);
        psum[part * 64 + q_] = lsum;
        __syncthreads();
        const float rinv = 1.f / (psum[q_] + psum[64 + q_] + psum[128 + q_] + psum[192 + q_]);
        #pragma unroll
        for (int k = 0; k < 16; ++k) {
            const int kk = part * 16 + k;
            pT[kk * 64 + q_] = __expf(sc[q_ * 65 + kk] * scale) * rinv;
        }
        __syncthreads();

        float oacc[4] = {0.f, 0.f, 0.f, 0.f};
        #pragma unroll 4
        for (int k4 = 0; k4 < 16; ++k4) {
            const float p0 = pT[(k4 * 4 + 0) * 64 + q_];
            const float p1 = pT[(k4 * 4 + 1) * 64 + q_];
            const float p2 = pT[(k4 * 4 + 2) * 64 + q_];
            const float p3 = pT[(k4 * 4 + 3) * 64 + q_];
            #pragma unroll
            for (int j = 0; j < 4; ++j) {
                const float4 vv = *reinterpret_cast<const float4*>(vh + (part * 4 + j) * QP + k4 * 4);
                oacc[j] = fmaf(p0, vv.x, oacc[j]);
                oacc[j] = fmaf(p1, vv.y, oacc[j]);
                oacc[j] = fmaf(p2, vv.z, oacc[j]);
                oacc[j] = fmaf(p3, vv.w, oacc[j]);
            }
        }
        __syncthreads();   // sc/pT reads done before next head rewrites

        // store attention-out directly as B fragments (t=q_, c=h*16+part*4+j)
        // c -> ks = h*2 + (part>>1), elem = part&1, frag-t4 = j
        {
            const int ks = h * 2 + (part >> 1);
            const int elem = part & 1;
            float* bhf = reinterpret_cast<float*>(bh2);
            float* blf = reinterpret_cast<float*>(bl2);
            #pragma unroll
            for (int j = 0; j < 4; ++j) {
                const int cell = ((q_ >> 3) * 16 + ks) * 32 + (q_ & 7) * 4 + j;
                uint32_t hi, lo;
                tf32_split(oacc[j], hi, lo);
                bhf[cell * 2 + elem] = __uint_as_float(hi);
                blf[cell * 2 + elem] = __uint_as_float(lo);
            }
        }
    }
    __syncthreads();   // ao frags complete

    // ---------- out = Wout @ ao + bout : chunks 6,7, write straight to GMEM ----------
    #pragma unroll 1
    for (int ch = 6; ch < 8; ++ch) {
        float d[4][4];
        gemm_chunk(ch, wrb, nhalf, lane, bh2, bl2, d);
        const int e0 = (ch - 6) * 64 + wrb * 16 + g;
        const float bb0 = __ldg(bout + e0);
        const float bb1 = __ldg(bout + e0 + 8);
        float* o0 = out + (size_t)b * CDIM * SDIM + (size_t)e0 * SDIM + n * 64 + nhalf * 32 + t4 * 2;
        float* o1 = o0 + (size_t)8 * SDIM;
        #pragma unroll
        for (int nt = 0; nt < 4; ++nt) {
            *reinterpret_cast<float2*>(o0 + nt * 8) = make_float2(d[nt][0] + bb0, d[nt][1] + bb0);
            *reinterpret_cast<float2*>(o1 + nt * 8) = make_float2(d[nt][2] + bb1, d[nt][3] + bb1);
        }
    }
}

extern "C" void kernel_launch(void* const* d_in, const int* in_sizes, int n_in,
                              void* d_out, int out_size)
{
    (void)in_sizes; (void)n_in; (void)out_size;
    const float* x    = (const float*)d_in[0];
    const float* Wqkv = (const float*)d_in[1];
    const float* Wout = (const float*)d_in[2];
    const float* bout = (const float*)d_in[3];
    float* out = (float*)d_out;

    prep_weights<<<64, 256>>>(Wqkv, Wout);

    cudaFuncSetAttribute(lwa3d_mma, cudaFuncAttributeMaxDynamicSharedMemorySize, SMEM_BYTES);
    dim3 grid(NWIN, 2);
    lwa3d_mma<<<grid, 256, SMEM_BYTES>>>(x, bout, out);
}

// round 5
// speedup vs baseline: 3.0827x; 1.2545x over previous
#include <cuda_runtime.h>
#include <cstdint>

// LocalWindowAttention3D: all-MMA (tf32 split) — QKV proj, QK^T, PV, out-proj.
// One CTA per (batch, window). 256 threads, ~201KB smem, 1 CTA/SM.

namespace {
constexpr int CDIM = 128;
constexpr int SDIM = 110592;      // 48^3
constexpr int NWIN = 1728;        // 12^3
constexpr int QTP  = 132;         // qT/kT token-major pitch (floats)
constexpr int VP   = 68;          // v channel-major pitch
constexpr int PP   = 72;          // pT pitch
constexpr int XP   = 72;          // xs gather pitch
// smem byte offsets
constexpr int O_QT  = 0;                    // 64*132*4 = 33792 (xs 36864 aliases QT+KT head)
constexpr int O_KT  = 33792;                // 33792
constexpr int O_VCM = 67584;                // 128*68*4 = 34816
constexpr int O_PTH = 102400;               // 64*72*4 = 18432
constexpr int O_PTL = 120832;               // 18432
constexpr int O_PS  = 139264;               // 128*4 = 512
constexpr int O_BH  = 139776;               // 4096 float2 = 32768
constexpr int O_BL  = 172544;               // 32768
constexpr int SMEM_BYTES = 172544 + 32768;  // 205312
}

// Weight fragment images: [ch(8)][wrb(4)][ks(16)][lane(32)] float4
// ch 0..5 = Wqkv (natural k-map: cols ks*8+t4, +4); ch 6..7 = Wout (paired
// k-map: cols ks*8+2*t4, +1 — matches attention-output fragment layout).
__device__ float4 gAh[8 * 4 * 16 * 32];
__device__ float4 gAl[8 * 4 * 16 * 32];

__device__ __forceinline__ uint32_t f2tf(float v) {
    uint32_t u; asm("cvt.rna.tf32.f32 %0, %1;" : "=r"(u) : "f"(v)); return u;
}
__device__ __forceinline__ void tf32_split(float v, uint32_t& hi, uint32_t& lo) {
    hi = f2tf(v);
    lo = f2tf(v - __uint_as_float(hi));
}
__device__ __forceinline__ void mma_tf32(float* d, uint32_t a0, uint32_t a1, uint32_t a2,
                                         uint32_t a3, uint32_t b0, uint32_t b1) {
    asm volatile(
        "mma.sync.aligned.m16n8k8.row.col.f32.tf32.tf32.f32 "
        "{%0,%1,%2,%3}, {%4,%5,%6,%7}, {%8,%9}, {%0,%1,%2,%3};"
        : "+f"(d[0]), "+f"(d[1]), "+f"(d[2]), "+f"(d[3])
        : "r"(a0), "r"(a1), "r"(a2), "r"(a3), "r"(b0), "r"(b1));
}

__global__ void prep_weights(const float* __restrict__ Wqkv, const float* __restrict__ Wout) {
    const int idx = blockIdx.x * 256 + threadIdx.x;     // 16384 frags
    const int lane = idx & 31;
    const int ks   = (idx >> 5) & 15;
    const int wrb  = (idx >> 9) & 3;
    const int ch   = idx >> 11;
    const int g = lane >> 2, t4 = lane & 3;
    const int e0 = ch * 64 + wrb * 16 + g;
    const float* W = (ch < 6) ? (Wqkv + (size_t)e0 * CDIM) : (Wout + (size_t)(e0 - 384) * CDIM);
    int cA, cB;
    if (ch < 6) { cA = ks * 8 + t4;     cB = cA + 4; }
    else        { cA = ks * 8 + t4 * 2; cB = cA + 1; }
    const float a[4] = {W[cA], W[8 * CDIM + cA], W[cB], W[8 * CDIM + cB]};
    float4 h, l;
    uint32_t hu, lu;
    tf32_split(a[0], hu, lu); h.x = __uint_as_float(hu); l.x = __uint_as_float(lu);
    tf32_split(a[1], hu, lu); h.y = __uint_as_float(hu); l.y = __uint_as_float(lu);
    tf32_split(a[2], hu, lu); h.z = __uint_as_float(hu); l.z = __uint_as_float(lu);
    tf32_split(a[3], hu, lu); h.w = __uint_as_float(hu); l.w = __uint_as_float(lu);
    gAh[idx] = h;
    gAl[idx] = l;
}

// One 64(e) x 64(t) x 128(c) GEMM chunk (A frags from gmem L2, B from smem).
__device__ __forceinline__ void gemm_chunk(int ch, int wrb, int nhalf, int lane,
                                           const float2* __restrict__ bh2,
                                           const float2* __restrict__ bl2,
                                           float (&d)[4][4])
{
    const float4* pah = gAh + ((ch * 4 + wrb) * 16) * 32 + lane;
    const float4* pal = gAl + ((ch * 4 + wrb) * 16) * 32 + lane;
    #pragma unroll
    for (int nt = 0; nt < 4; ++nt)
        #pragma unroll
        for (int j = 0; j < 4; ++j) d[nt][j] = 0.f;

    #pragma unroll
    for (int ks = 0; ks < 16; ++ks) {
        const float4 ah = __ldg(pah + ks * 32);
        const float4 al = __ldg(pal + ks * 32);
        const uint32_t ah0 = __float_as_uint(ah.x), ah1 = __float_as_uint(ah.y);
        const uint32_t ah2 = __float_as_uint(ah.z), ah3 = __float_as_uint(ah.w);
        const uint32_t al0 = __float_as_uint(al.x), al1 = __float_as_uint(al.y);
        const uint32_t al2 = __float_as_uint(al.z), al3 = __float_as_uint(al.w);
        #pragma unroll
        for (int nt = 0; nt < 4; ++nt) {
            const int ci = ((nhalf * 4 + nt) * 16 + ks) * 32 + lane;
            const float2 vbh = bh2[ci];
            const float2 vbl = bl2[ci];
            const uint32_t bh0 = __float_as_uint(vbh.x), bh1 = __float_as_uint(vbh.y);
            const uint32_t bl0 = __float_as_uint(vbl.x), bl1 = __float_as_uint(vbl.y);
            mma_tf32(d[nt], ah0, ah1, ah2, ah3, bh0, bh1);
            mma_tf32(d[nt], ah0, ah1, ah2, ah3, bl0, bl1);
            mma_tf32(d[nt], al0, al1, al2, al3, bh0, bh1);
        }
    }
}

__global__ __launch_bounds__(256, 1)
void lwa3d_mma(const float* __restrict__ x, const float* __restrict__ bout,
               float* __restrict__ out)
{
    extern __shared__ char smc[];
    float* qT  = reinterpret_cast<float*>(smc + O_QT);    // [64 tok][132] (Q pre-scaled)
    float* kT  = reinterpret_cast<float*>(smc + O_KT);    // [64 tok][132]
    float* vcm = reinterpret_cast<float*>(smc + O_VCM);   // [128 ch][68]
    float* pTh = reinterpret_cast<float*>(smc + O_PTH);   // [64 q][72]
    float* pTl = reinterpret_cast<float*>(smc + O_PTL);   // [64 q][72]
    float* ps  = reinterpret_cast<float*>(smc + O_PS);    // [2][64]
    float* xs  = reinterpret_cast<float*>(smc + O_QT);    // gather scratch (alias)
    float2* bh2 = reinterpret_cast<float2*>(smc + O_BH);
    float2* bl2 = reinterpret_cast<float2*>(smc + O_BL);

    const int tid  = threadIdx.x;
    const int wid  = tid >> 5;
    const int lane = tid & 31;
    const int g    = lane >> 2;
    const int t4   = lane & 3;
    const int wrb  = wid >> 1;
    const int nhalf = wid & 1;
    const int n = blockIdx.x;
    const int b = blockIdx.y;
    const float scale = 0.08838834764831845f;   // 128^-0.5

    // ---------- gather x window into xs [128c][64t] ----------
    {
        const int ndi = n / 144, nhi = (n / 12) % 12, nwi = n % 12;
        const float* xb = x + (size_t)b * CDIM * SDIM;
        const int sbase = ((ndi * 4) * 48 + nhi * 4) * 48 + nwi * 4;
        for (int i = tid; i < CDIM * 16; i += 256) {
            const int c = i >> 4;
            const int gg = i & 15;
            const int s0 = sbase + ((gg >> 2) * 48 + (gg & 3)) * 48;
            *reinterpret_cast<float4*>(xs + c * XP + gg * 4) =
                *reinterpret_cast<const float4*>(xb + (size_t)c * SDIM + s0);
        }
    }
    __syncthreads();

    // ---------- build tf32 hi/lo B fragments from xs ----------
    for (int cell = tid; cell < 4096; cell += 256) {
        const int l2 = cell & 31;
        const int ks = (cell >> 5) & 15;
        const int tb = cell >> 9;
        const int t  = tb * 8 + (l2 >> 2);
        const int c0 = ks * 8 + (l2 & 3);
        uint32_t h0, l0, h1, l1;
        tf32_split(xs[c0 * XP + t], h0, l0);
        tf32_split(xs[(c0 + 4) * XP + t], h1, l1);
        bh2[cell] = make_float2(__uint_as_float(h0), __uint_as_float(h1));
        bl2[cell] = make_float2(__uint_as_float(l0), __uint_as_float(l1));
    }
    __syncthreads();

    // ---------- QKV = Wqkv @ x : Q,K -> token-major; V -> channel-major ----------
    #pragma unroll 1
    for (int ch = 0; ch < 6; ++ch) {
        float d[4][4];
        gemm_chunk(ch, wrb, nhalf, lane, bh2, bl2, d);
        const int e0 = (ch & 1) * 64 + wrb * 16 + g;   // channel within section
        const int t0 = nhalf * 32 + t4 * 2;
        if (ch < 2) {            // Q: pre-scaled token-major
            #pragma unroll
            for (int nt = 0; nt < 4; ++nt) {
                const int t = t0 + nt * 8;
                qT[t * QTP + e0]           = d[nt][0] * scale;
                qT[(t + 1) * QTP + e0]     = d[nt][1] * scale;
                qT[t * QTP + e0 + 8]       = d[nt][2] * scale;
                qT[(t + 1) * QTP + e0 + 8] = d[nt][3] * scale;
            }
        } else if (ch < 4) {     // K: token-major
            #pragma unroll
            for (int nt = 0; nt < 4; ++nt) {
                const int t = t0 + nt * 8;
                kT[t * QTP + e0]           = d[nt][0];
                kT[(t + 1) * QTP + e0]     = d[nt][1];
                kT[t * QTP + e0 + 8]       = d[nt][2];
                kT[(t + 1) * QTP + e0 + 8] = d[nt][3];
            }
        } else {                 // V: channel-major
            float* v0 = vcm + e0 * VP + t0;
            float* v1 = v0 + 8 * VP;
            #pragma unroll
            for (int nt = 0; nt < 4; ++nt) {
                *reinterpret_cast<float2*>(v0 + nt * 8) = make_float2(d[nt][0], d[nt][1]);
                *reinterpret_cast<float2*>(v1 + nt * 8) = make_float2(d[nt][2], d[nt][3]);
            }
        }
    }
    __syncthreads();

    // ---------- MMA attention ----------
    // scores: warp = (mb = wid>>1, nh = wid&1): S tile 16q x 32k
    // PV:     warp = (mbp = wid&3, nhd = wid>>2): O tile 16q x 8hd
    const int mb  = wid >> 1;
    const int nh  = wid & 1;
    const int mbp = wid & 3;
    const int nhd = wid >> 2;

    #pragma unroll 1
    for (int h = 0; h < 8; ++h) {
        // ---- S = Q K^T (scaled), 3x tf32 split ----
        float d[4][4];
        #pragma unroll
        for (int nt = 0; nt < 4; ++nt)
            #pragma unroll
            for (int j = 0; j < 4; ++j) d[nt][j] = 0.f;

        #pragma unroll
        for (int ks = 0; ks < 2; ++ks) {
            const int cA = h * 16 + ks * 8 + t4;
            const float* q0 = qT + (mb * 16 + g) * QTP + cA;
            uint32_t ah[4], al[4];
            tf32_split(q0[0],            ah[0], al[0]);
            tf32_split(q0[8 * QTP],      ah[1], al[1]);
            tf32_split(q0[4],            ah[2], al[2]);
            tf32_split(q0[8 * QTP + 4],  ah[3], al[3]);
            #pragma unroll
            for (int nt = 0; nt < 4; ++nt) {
                const float* k0 = kT + (nh * 32 + nt * 8 + g) * QTP + cA;
                uint32_t bh0, bl0, bh1, bl1;
                tf32_split(k0[0], bh0, bl0);
                tf32_split(k0[4], bh1, bl1);
                mma_tf32(d[nt], ah[0], ah[1], ah[2], ah[3], bh0, bh1);
                mma_tf32(d[nt], ah[0], ah[1], ah[2], ah[3], bl0, bl1);
                mma_tf32(d[nt], al[0], al[1], al[2], al[3], bh0, bh1);
            }
        }

        // ---- exp (unnormalized P) + row sums ----
        float e[4][4];
        float s0 = 0.f, s1 = 0.f;
        #pragma unroll
        for (int nt = 0; nt < 4; ++nt) {
            e[nt][0] = __expf(d[nt][0]);
            e[nt][1] = __expf(d[nt][1]);
            e[nt][2] = __expf(d[nt][2]);
            e[nt][3] = __expf(d[nt][3]);
            s0 += e[nt][0] + e[nt][1];
            s1 += e[nt][2] + e[nt][3];
        }
        s0 += __shfl_xor_sync(0xFFFFFFFF, s0, 1);
        s0 += __shfl_xor_sync(0xFFFFFFFF, s0, 2);
        s1 += __shfl_xor_sync(0xFFFFFFFF, s1, 1);
        s1 += __shfl_xor_sync(0xFFFFFFFF, s1, 2);
        if (t4 == 0) {
            ps[nh * 64 + mb * 16 + g]     = s0;
            ps[nh * 64 + mb * 16 + g + 8] = s1;
        }

        // ---- write P hi/lo to pT[q][kt] (2-term split) ----
        {
            const int q0r = mb * 16 + g;
            const int kt0 = nh * 32 + t4 * 2;
            #pragma unroll
            for (int nt = 0; nt < 4; ++nt) {
                const int kt = kt0 + nt * 8;
                uint32_t h0, l0, h1, l1;
                tf32_split(e[nt][0], h0, l0);
                tf32_split(e[nt][1], h1, l1);
                *reinterpret_cast<float2*>(pTh + q0r * PP + kt) =
                    make_float2(__uint_as_float(h0), __uint_as_float(h1));
                *reinterpret_cast<float2*>(pTl + q0r * PP + kt) =
                    make_float2(__uint_as_float(l0), __uint_as_float(l1));
                tf32_split(e[nt][2], h0, l0);
                tf32_split(e[nt][3], h1, l1);
                *reinterpret_cast<float2*>(pTh + (q0r + 8) * PP + kt) =
                    make_float2(__uint_as_float(h0), __uint_as_float(h1));
                *reinterpret_cast<float2*>(pTl + (q0r + 8) * PP + kt) =
                    make_float2(__uint_as_float(l0), __uint_as_float(l1));
            }
        }
        __syncthreads();

        // ---- O = P V (3-term: PhVh + PhVl + PlVh), two accum chains ----
        float oa[4] = {0.f, 0.f, 0.f, 0.f};
        float ob[4] = {0.f, 0.f, 0.f, 0.f};
        #pragma unroll
        for (int ks = 0; ks < 8; ++ks) {
            const float* p0 = pTh + (mbp * 16 + g) * PP + ks * 8 + t4;
            const float* p1 = pTl + (mbp * 16 + g) * PP + ks * 8 + t4;
            const uint32_t ph0 = __float_as_uint(p0[0]);
            const uint32_t ph1 = __float_as_uint(p0[8 * PP]);
            const uint32_t ph2 = __float_as_uint(p0[4]);
            const uint32_t ph3 = __float_as_uint(p0[8 * PP + 4]);
            const uint32_t pl0 = __float_as_uint(p1[0]);
            const uint32_t pl1 = __float_as_uint(p1[8 * PP]);
            const uint32_t pl2 = __float_as_uint(p1[4]);
            const uint32_t pl3 = __float_as_uint(p1[8 * PP + 4]);
            const float* vp = vcm + (h * 16 + nhd * 8 + g) * VP + ks * 8 + t4;
            uint32_t vh0, vl0, vh1, vl1;
            tf32_split(vp[0], vh0, vl0);
            tf32_split(vp[4], vh1, vl1);
            float* acc = (ks & 1) ? ob : oa;
            mma_tf32(acc, ph0, ph1, ph2, ph3, vh0, vh1);
            mma_tf32(acc, ph0, ph1, ph2, ph3, vl0, vl1);
            mma_tf32(acc, pl0, pl1, pl2, pl3, vh0, vh1);
        }
        #pragma unroll
        for (int j = 0; j < 4; ++j) oa[j] += ob[j];

        // ---- normalize + store as out-proj B fragments ----
        {
            const int q0r = mbp * 16 + g;
            const float r0 = 1.f / (ps[q0r] + ps[64 + q0r]);
            const float r1 = 1.f / (ps[q0r + 8] + ps[64 + q0r + 8]);
            const int ksp = 2 * h + nhd;
            const int cellA = (2 * mbp * 16 + ksp) * 32 + g * 4 + t4;
            const int cellB = ((2 * mbp + 1) * 16 + ksp) * 32 + g * 4 + t4;
            uint32_t h0, l0, h1, l1;
            tf32_split(oa[0] * r0, h0, l0);
            tf32_split(oa[1] * r0, h1, l1);
            bh2[cellA] = make_float2(__uint_as_float(h0), __uint_as_float(h1));
            bl2[cellA] = make_float2(__uint_as_float(l0), __uint_as_float(l1));
            tf32_split(oa[2] * r1, h0, l0);
            tf32_split(oa[3] * r1, h1, l1);
            bh2[cellB] = make_float2(__uint_as_float(h0), __uint_as_float(h1));
            bl2[cellB] = make_float2(__uint_as_float(l0), __uint_as_float(l1));
        }
        __syncthreads();   // protect pT/ps before next head
    }

    // ---------- out = Wout @ ao + bout : chunks 6,7 -> GMEM ----------
    #pragma unroll 1
    for (int ch = 6; ch < 8; ++ch) {
        float d[4][4];
        gemm_chunk(ch, wrb, nhalf, lane, bh2, bl2, d);
        const int e0 = (ch - 6) * 64 + wrb * 16 + g;
        const float bb0 = __ldg(bout + e0);
        const float bb1 = __ldg(bout + e0 + 8);
        float* o0 = out + (size_t)b * CDIM * SDIM + (size_t)e0 * SDIM + n * 64 + nhalf * 32 + t4 * 2;
        float* o1 = o0 + (size_t)8 * SDIM;
        #pragma unroll
        for (int nt = 0; nt < 4; ++nt) {
            *reinterpret_cast<float2*>(o0 + nt * 8) = make_float2(d[nt][0] + bb0, d[nt][1] + bb0);
            *reinterpret_cast<float2*>(o1 + nt * 8) = make_float2(d[nt][2] + bb1, d[nt][3] + bb1);
        }
    }
}

extern "C" void kernel_launch(void* const* d_in, const int* in_sizes, int n_in,
                              void* d_out, int out_size)
{
    (void)in_sizes; (void)n_in; (void)out_size;
    const float* x    = (const float*)d_in[0];
    const float* Wqkv = (const float*)d_in[1];
    const float* Wout = (const float*)d_in[2];
    const float* bout = (const float*)d_in[3];
    float* out = (float*)d_out;

    prep_weights<<<64, 256>>>(Wqkv, Wout);

    cudaFuncSetAttribute(lwa3d_mma, cudaFuncAttributeMaxDynamicSharedMemorySize, SMEM_BYTES);
    dim3 grid(NWIN, 2);
    lwa3d_mma<<<grid, 256, SMEM_BYTES>>>(x, bout, out);
}

// round 6
// speedup vs baseline: 3.2809x; 1.0643x over previous
#include <cuda_runtime.h>
#include <cstdint>

// LocalWindowAttention3D: all-MMA (tf32 split), 512 threads/CTA, 2-head attention.
// One CTA per (batch, window). ~201KB smem, 1 CTA/SM, 16 warps.

namespace {
constexpr int CDIM = 128;
constexpr int SDIM = 110592;      // 48^3
constexpr int NWIN = 1728;        // 12^3
constexpr int QTP  = 132;         // qT/kT token-major pitch (floats)
constexpr int VP   = 68;          // v channel-major pitch
constexpr int PP   = 72;          // pT pitch
constexpr int XP   = 72;          // xs gather pitch
// smem byte offsets
constexpr int O_QT  = 0;                    // 64*132*4 = 33792 (xs aliases QT+KT head)
constexpr int O_KT  = 33792;                // 33792
constexpr int O_VCM = 67584;                // 128*68*4 = 34816
constexpr int O_PT  = 102400;               // 2 heads * 64*72*4 = 36864 (fp32 P)
constexpr int O_PS  = 139264;               // 2*2*64*4 = 1024
constexpr int O_BH  = 140288;               // 4096 float2 = 32768
constexpr int O_BL  = 173056;               // 32768
constexpr int SMEM_BYTES = 173056 + 32768;  // 205824
}

// Weight fragment images: [ch(8)][wrb(4)][ks(16)][lane(32)] float4
// ch 0..5 = Wqkv (k-map: cols ks*8+t4, +4); ch 6..7 = Wout (paired k-map:
// cols ks*8+2*t4, +1 — matches attention-output fragment layout).
__device__ float4 gAh[8 * 4 * 16 * 32];
__device__ float4 gAl[8 * 4 * 16 * 32];

__device__ __forceinline__ uint32_t f2tf(float v) {
    uint32_t u; asm("cvt.rna.tf32.f32 %0, %1;" : "=r"(u) : "f"(v)); return u;
}
__device__ __forceinline__ void tf32_split(float v, uint32_t& hi, uint32_t& lo) {
    hi = f2tf(v);
    lo = f2tf(v - __uint_as_float(hi));
}
__device__ __forceinline__ void mma_tf32(float* d, uint32_t a0, uint32_t a1, uint32_t a2,
                                         uint32_t a3, uint32_t b0, uint32_t b1) {
    asm volatile(
        "mma.sync.aligned.m16n8k8.row.col.f32.tf32.tf32.f32 "
        "{%0,%1,%2,%3}, {%4,%5,%6,%7}, {%8,%9}, {%0,%1,%2,%3};"
        : "+f"(d[0]), "+f"(d[1]), "+f"(d[2]), "+f"(d[3])
        : "r"(a0), "r"(a1), "r"(a2), "r"(a3), "r"(b0), "r"(b1));
}

__global__ void prep_weights(const float* __restrict__ Wqkv, const float* __restrict__ Wout) {
    const int idx = blockIdx.x * 256 + threadIdx.x;     // 16384 frags
    const int lane = idx & 31;
    const int ks   = (idx >> 5) & 15;
    const int wrb  = (idx >> 9) & 3;
    const int ch   = idx >> 11;
    const int g = lane >> 2, t4 = lane & 3;
    const int e0 = ch * 64 + wrb * 16 + g;
    const float* W = (ch < 6) ? (Wqkv + (size_t)e0 * CDIM) : (Wout + (size_t)(e0 - 384) * CDIM);
    int cA, cB;
    if (ch < 6) { cA = ks * 8 + t4;     cB = cA + 4; }
    else        { cA = ks * 8 + t4 * 2; cB = cA + 1; }
    const float a[4] = {W[cA], W[8 * CDIM + cA], W[cB], W[8 * CDIM + cB]};
    float4 h, l;
    uint32_t hu, lu;
    tf32_split(a[0], hu, lu); h.x = __uint_as_float(hu); l.x = __uint_as_float(lu);
    tf32_split(a[1], hu, lu); h.y = __uint_as_float(hu); l.y = __uint_as_float(lu);
    tf32_split(a[2], hu, lu); h.z = __uint_as_float(hu); l.z = __uint_as_float(lu);
    tf32_split(a[3], hu, lu); h.w = __uint_as_float(hu); l.w = __uint_as_float(lu);
    gAh[idx] = h;
    gAl[idx] = l;
}

// One 64(e) x 64(t) x 128(c) GEMM warp-tile (A frags from gmem L2, B from smem).
__device__ __forceinline__ void gemm_chunk(int ch, int wrb, int nhalf, int lane,
                                           const float2* __restrict__ bh2,
                                           const float2* __restrict__ bl2,
                                           float (&d)[4][4])
{
    const float4* pah = gAh + ((ch * 4 + wrb) * 16) * 32 + lane;
    const float4* pal = gAl + ((ch * 4 + wrb) * 16) * 32 + lane;
    #pragma unroll
    for (int nt = 0; nt < 4; ++nt)
        #pragma unroll
        for (int j = 0; j < 4; ++j) d[nt][j] = 0.f;

    #pragma unroll
    for (int ks = 0; ks < 16; ++ks) {
        const float4 ah = __ldg(pah + ks * 32);
        const float4 al = __ldg(pal + ks * 32);
        const uint32_t ah0 = __float_as_uint(ah.x), ah1 = __float_as_uint(ah.y);
        const uint32_t ah2 = __float_as_uint(ah.z), ah3 = __float_as_uint(ah.w);
        const uint32_t al0 = __float_as_uint(al.x), al1 = __float_as_uint(al.y);
        const uint32_t al2 = __float_as_uint(al.z), al3 = __float_as_uint(al.w);
        #pragma unroll
        for (int nt = 0; nt < 4; ++nt) {
            const int ci = ((nhalf * 4 + nt) * 16 + ks) * 32 + lane;
            const float2 vbh = bh2[ci];
            const float2 vbl = bl2[ci];
            const uint32_t bh0 = __float_as_uint(vbh.x), bh1 = __float_as_uint(vbh.y);
            const uint32_t bl0 = __float_as_uint(vbl.x), bl1 = __float_as_uint(vbl.y);
            mma_tf32(d[nt], ah0, ah1, ah2, ah3, bh0, bh1);
            mma_tf32(d[nt], ah0, ah1, ah2, ah3, bl0, bl1);
            mma_tf32(d[nt], al0, al1, al2, al3, bh0, bh1);
        }
    }
}

__global__ __launch_bounds__(512, 1)
void lwa3d_mma(const float* __restrict__ x, const float* __restrict__ bout,
               float* __restrict__ out)
{
    extern __shared__ char smc[];
    float* qT  = reinterpret_cast<float*>(smc + O_QT);    // [64 tok][132] (Q pre-scaled)
    float* kT  = reinterpret_cast<float*>(smc + O_KT);    // [64 tok][132]
    float* vcm = reinterpret_cast<float*>(smc + O_VCM);   // [128 ch][68]
    float* pT0 = reinterpret_cast<float*>(smc + O_PT);    // [2 heads][64 q][72] fp32
    float* ps  = reinterpret_cast<float*>(smc + O_PS);    // [2 heads][2][64]
    float* xs  = reinterpret_cast<float*>(smc + O_QT);    // gather scratch (alias)
    float2* bh2 = reinterpret_cast<float2*>(smc + O_BH);
    float2* bl2 = reinterpret_cast<float2*>(smc + O_BL);

    const int tid  = threadIdx.x;
    const int wid  = tid >> 5;
    const int lane = tid & 31;
    const int g    = lane >> 2;
    const int t4   = lane & 3;
    const int n = blockIdx.x;
    const int b = blockIdx.y;
    const float scale = 0.08838834764831845f;   // 128^-0.5

    // ---------- gather x window into xs [128c][64t] ----------
    {
        const int ndi = n / 144, nhi = (n / 12) % 12, nwi = n % 12;
        const float* xb = x + (size_t)b * CDIM * SDIM;
        const int sbase = ((ndi * 4) * 48 + nhi * 4) * 48 + nwi * 4;
        for (int i = tid; i < CDIM * 16; i += 512) {
            const int c = i >> 4;
            const int gg = i & 15;
            const int s0 = sbase + ((gg >> 2) * 48 + (gg & 3)) * 48;
            *reinterpret_cast<float4*>(xs + c * XP + gg * 4) =
                *reinterpret_cast<const float4*>(xb + (size_t)c * SDIM + s0);
        }
    }
    __syncthreads();

    // ---------- build tf32 hi/lo B fragments from xs ----------
    for (int cell = tid; cell < 4096; cell += 512) {
        const int l2 = cell & 31;
        const int ks = (cell >> 5) & 15;
        const int tb = cell >> 9;
        const int t  = tb * 8 + (l2 >> 2);
        const int c0 = ks * 8 + (l2 & 3);
        uint32_t h0, l0, h1, l1;
        tf32_split(xs[c0 * XP + t], h0, l0);
        tf32_split(xs[(c0 + 4) * XP + t], h1, l1);
        bh2[cell] = make_float2(__uint_as_float(h0), __uint_as_float(h1));
        bl2[cell] = make_float2(__uint_as_float(l0), __uint_as_float(l1));
    }
    __syncthreads();

    // ---------- QKV = Wqkv @ x : 48 warp-tasks, 3 per warp ----------
    #pragma unroll 1
    for (int i = 0; i < 3; ++i) {
        const int task  = wid * 3 + i;
        const int ch    = task >> 3;
        const int wrb   = (task >> 1) & 3;
        const int nhalf = task & 1;
        float d[4][4];
        gemm_chunk(ch, wrb, nhalf, lane, bh2, bl2, d);
        const int e0 = (ch & 1) * 64 + wrb * 16 + g;   // channel within section
        const int t0 = nhalf * 32 + t4 * 2;
        if (ch < 2) {            // Q: pre-scaled token-major
            #pragma unroll
            for (int nt = 0; nt < 4; ++nt) {
                const int t = t0 + nt * 8;
                qT[t * QTP + e0]           = d[nt][0] * scale;
                qT[(t + 1) * QTP + e0]     = d[nt][1] * scale;
                qT[t * QTP + e0 + 8]       = d[nt][2] * scale;
                qT[(t + 1) * QTP + e0 + 8] = d[nt][3] * scale;
            }
        } else if (ch < 4) {     // K: token-major
            #pragma unroll
            for (int nt = 0; nt < 4; ++nt) {
                const int t = t0 + nt * 8;
                kT[t * QTP + e0]           = d[nt][0];
                kT[(t + 1) * QTP + e0]     = d[nt][1];
                kT[t * QTP + e0 + 8]       = d[nt][2];
                kT[(t + 1) * QTP + e0 + 8] = d[nt][3];
            }
        } else {                 // V: channel-major
            float* v0 = vcm + e0 * VP + t0;
            float* v1 = v0 + 8 * VP;
            #pragma unroll
            for (int nt = 0; nt < 4; ++nt) {
                *reinterpret_cast<float2*>(v0 + nt * 8) = make_float2(d[nt][0], d[nt][1]);
                *reinterpret_cast<float2*>(v1 + nt * 8) = make_float2(d[nt][2], d[nt][3]);
            }
        }
    }
    __syncthreads();

    // ---------- MMA attention: 2 heads in flight ----------
    const int hsel = wid >> 3;          // which of the 2 concurrent heads
    const int sub  = wid & 7;
    const int mb  = sub >> 1;           // QK: 16q row-block
    const int nh  = sub & 1;            // QK: 32k col-half
    const int mbp = sub & 3;            // PV: 16q row-block
    const int nhd = sub >> 2;           // PV: 8hd col-half
    float* pT  = pT0 + hsel * 64 * PP;
    float* psh = ps + hsel * 128;

    #pragma unroll 1
    for (int hh = 0; hh < 4; ++hh) {
        const int h = hh * 2 + hsel;

        // ---- S = Q K^T (scaled), 3x tf32 split ----
        float d[4][4];
        #pragma unroll
        for (int nt = 0; nt < 4; ++nt)
            #pragma unroll
            for (int j = 0; j < 4; ++j) d[nt][j] = 0.f;

        #pragma unroll
        for (int ks = 0; ks < 2; ++ks) {
            const int cA = h * 16 + ks * 8 + t4;
            const float* q0 = qT + (mb * 16 + g) * QTP + cA;
            uint32_t ah[4], al[4];
            tf32_split(q0[0],            ah[0], al[0]);
            tf32_split(q0[8 * QTP],      ah[1], al[1]);
            tf32_split(q0[4],            ah[2], al[2]);
            tf32_split(q0[8 * QTP + 4],  ah[3], al[3]);
            #pragma unroll
            for (int nt = 0; nt < 4; ++nt) {
                const float* k0 = kT + (nh * 32 + nt * 8 + g) * QTP + cA;
                uint32_t bh0, bl0, bh1, bl1;
                tf32_split(k0[0], bh0, bl0);
                tf32_split(k0[4], bh1, bl1);
                mma_tf32(d[nt], ah[0], ah[1], ah[2], ah[3], bh0, bh1);
                mma_tf32(d[nt], ah[0], ah[1], ah[2], ah[3], bl0, bl1);
                mma_tf32(d[nt], al[0], al[1], al[2], al[3], bh0, bh1);
            }
        }

        // ---- exp (unnormalized P) + row sums ----
        float e[4][4];
        float s0 = 0.f, s1 = 0.f;
        #pragma unroll
        for (int nt = 0; nt < 4; ++nt) {
            e[nt][0] = __expf(d[nt][0]);
            e[nt][1] = __expf(d[nt][1]);
            e[nt][2] = __expf(d[nt][2]);
            e[nt][3] = __expf(d[nt][3]);
            s0 += e[nt][0] + e[nt][1];
            s1 += e[nt][2] + e[nt][3];
        }
        s0 += __shfl_xor_sync(0xFFFFFFFF, s0, 1);
        s0 += __shfl_xor_sync(0xFFFFFFFF, s0, 2);
        s1 += __shfl_xor_sync(0xFFFFFFFF, s1, 1);
        s1 += __shfl_xor_sync(0xFFFFFFFF, s1, 2);
        if (t4 == 0) {
            psh[nh * 64 + mb * 16 + g]     = s0;
            psh[nh * 64 + mb * 16 + g + 8] = s1;
        }

        // ---- write P (fp32) to pT[q][kt] ----
        {
            const int q0r = mb * 16 + g;
            const int kt0 = nh * 32 + t4 * 2;
            #pragma unroll
            for (int nt = 0; nt < 4; ++nt) {
                const int kt = kt0 + nt * 8;
                *reinterpret_cast<float2*>(pT + q0r * PP + kt)       = make_float2(e[nt][0], e[nt][1]);
                *reinterpret_cast<float2*>(pT + (q0r + 8) * PP + kt) = make_float2(e[nt][2], e[nt][3]);
            }
        }
        __syncthreads();

        // ---- O = P V (3-term split), two accum chains ----
        float oa[4] = {0.f, 0.f, 0.f, 0.f};
        float ob[4] = {0.f, 0.f, 0.f, 0.f};
        #pragma unroll
        for (int ks = 0; ks < 8; ++ks) {
            const float* p0 = pT + (mbp * 16 + g) * PP + ks * 8 + t4;
            uint32_t ph0, pl0, ph1, pl1, ph2, pl2, ph3, pl3;
            tf32_split(p0[0],           ph0, pl0);
            tf32_split(p0[8 * PP],      ph1, pl1);
            tf32_split(p0[4],           ph2, pl2);
            tf32_split(p0[8 * PP + 4],  ph3, pl3);
            const float* vp = vcm + (h * 16 + nhd * 8 + g) * VP + ks * 8 + t4;
            uint32_t vh0, vl0, vh1, vl1;
            tf32_split(vp[0], vh0, vl0);
            tf32_split(vp[4], vh1, vl1);
            float* acc = (ks & 1) ? ob : oa;
            mma_tf32(acc, ph0, ph1, ph2, ph3, vh0, vh1);
            mma_tf32(acc, ph0, ph1, ph2, ph3, vl0, vl1);
            mma_tf32(acc, pl0, pl1, pl2, pl3, vh0, vh1);
        }
        #pragma unroll
        for (int j = 0; j < 4; ++j) oa[j] += ob[j];

        // ---- normalize + store as out-proj B fragments ----
        {
            const int q0r = mbp * 16 + g;
            const float r0 = 1.f / (psh[q0r] + psh[64 + q0r]);
            const float r1 = 1.f / (psh[q0r + 8] + psh[64 + q0r + 8]);
            const int ksp = 2 * h + nhd;
            const int cellA = (2 * mbp * 16 + ksp) * 32 + g * 4 + t4;
            const int cellB = ((2 * mbp + 1) * 16 + ksp) * 32 + g * 4 + t4;
            uint32_t h0, l0, h1, l1;
            tf32_split(oa[0] * r0, h0, l0);
            tf32_split(oa[1] * r0, h1, l1);
            bh2[cellA] = make_float2(__uint_as_float(h0), __uint_as_float(h1));
            bl2[cellA] = make_float2(__uint_as_float(l0), __uint_as_float(l1));
            tf32_split(oa[2] * r1, h0, l0);
            tf32_split(oa[3] * r1, h1, l1);
            bh2[cellB] = make_float2(__uint_as_float(h0), __uint_as_float(h1));
            bl2[cellB] = make_float2(__uint_as_float(l0), __uint_as_float(l1));
        }
        __syncthreads();   // protect pT/ps before next head pair
    }

    // ---------- out = Wout @ ao + bout : 16 warp-tasks, 1 per warp ----------
    {
        const int ch    = 6 + (wid >> 3);
        const int wrb   = (wid >> 1) & 3;
        const int nhalf = wid & 1;
        float d[4][4];
        gemm_chunk(ch, wrb, nhalf, lane, bh2, bl2, d);
        const int e0 = (ch - 6) * 64 + wrb * 16 + g;
        const float bb0 = __ldg(bout + e0);
        const float bb1 = __ldg(bout + e0 + 8);
        float* o0 = out + (size_t)b * CDIM * SDIM + (size_t)e0 * SDIM + n * 64 + nhalf * 32 + t4 * 2;
        float* o1 = o0 + (size_t)8 * SDIM;
        #pragma unroll
        for (int nt = 0; nt < 4; ++nt) {
            *reinterpret_cast<float2*>(o0 + nt * 8) = make_float2(d[nt][0] + bb0, d[nt][1] + bb0);
            *reinterpret_cast<float2*>(o1 + nt * 8) = make_float2(d[nt][2] + bb1, d[nt][3] + bb1);
        }
    }
}

extern "C" void kernel_launch(void* const* d_in, const int* in_sizes, int n_in,
                              void* d_out, int out_size)
{
    (void)in_sizes; (void)n_in; (void)out_size;
    const float* x    = (const float*)d_in[0];
    const float* Wqkv = (const float*)d_in[1];
    const float* Wout = (const float*)d_in[2];
    const float* bout = (const float*)d_in[3];
    float* out = (float*)d_out;

    prep_weights<<<64, 256>>>(Wqkv, Wout);

    cudaFuncSetAttribute(lwa3d_mma, cudaFuncAttributeMaxDynamicSharedMemorySize, SMEM_BYTES);
    dim3 grid(NWIN, 2);
    lwa3d_mma<<<grid, 512, SMEM_BYTES>>>(x, bout, out);
}

// round 7
// speedup vs baseline: 5.1787x; 1.5784x over previous
#include <cuda_runtime.h>
#include <cuda_bf16.h>
#include <cstdint>

// LocalWindowAttention3D: all-MMA bf16 m16n8k16 (3-term split), 512 thr/CTA.
// One CTA per (batch, window), ~167KB smem, 1 CTA/SM, 16 warps.

namespace {
constexpr int CDIM = 128;
constexpr int SDIM = 110592;      // 48^3
constexpr int NWIN = 1728;        // 12^3
constexpr int QTP  = 132;         // qT/kT token-major pitch (floats)
constexpr int VP   = 68;          // v channel-major pitch
constexpr int PP   = 68;          // pT pitch (68 = conflict-free for t4-stride loads)
constexpr int XP   = 72;          // xs gather pitch
// smem byte offsets
constexpr int O_QT  = 0;                    // 64*132*4 = 33792 (xs alias spans QT+KT head)
constexpr int O_KT  = 33792;                // 33792
constexpr int O_VCM = 67584;                // 128*68*4 = 34816
constexpr int O_PT  = 102400;               // 2 heads * 64*68*4 = 34816 (fp32 P)
constexpr int O_PS  = 137216;               // 1024
constexpr int O_BH  = 138240;               // 2048 uint2 = 16384
constexpr int O_BL  = 154624;               // 16384
constexpr int SMEM_BYTES = 154624 + 16384;  // 171008
}

// Weight fragment images: [ch(8)][wrb(4)][ks(8)][lane(32)] uint4 = a0..a3 bf16x2.
// ch 0..5 = Wqkv, k-map pairs (c0+t4, c0+t4+4), (c0+8+t4, c0+12+t4).
// ch 6..7 = Wout, k-map pairs (c0+2t4, c0+2t4+1), (c0+2t4+8, c0+2t4+9)
//           — matches attention-output D-fragment pairs.
__device__ uint4 gWh[8 * 4 * 8 * 32];
__device__ uint4 gWl[8 * 4 * 8 * 32];

// pack two floats -> bf16x2 (a in low half, b in high half) + residual pair
__device__ __forceinline__ void split2(float a, float b, uint32_t& hi, uint32_t& lo) {
    __nv_bfloat162 h = __floats2bfloat162_rn(a, b);
    const float ra = a - __low2float(h);
    const float rb = b - __high2float(h);
    __nv_bfloat162 l = __floats2bfloat162_rn(ra, rb);
    hi = *reinterpret_cast<uint32_t*>(&h);
    lo = *reinterpret_cast<uint32_t*>(&l);
}
__device__ __forceinline__ uint32_t pack2(float a, float b) {
    __nv_bfloat162 h = __floats2bfloat162_rn(a, b);
    return *reinterpret_cast<uint32_t*>(&h);
}
__device__ __forceinline__ void mma_bf16(float* d, uint32_t a0, uint32_t a1, uint32_t a2,
                                         uint32_t a3, uint32_t b0, uint32_t b1) {
    asm volatile(
        "mma.sync.aligned.m16n8k16.row.col.f32.bf16.bf16.f32 "
        "{%0,%1,%2,%3}, {%4,%5,%6,%7}, {%8,%9}, {%0,%1,%2,%3};"
        : "+f"(d[0]), "+f"(d[1]), "+f"(d[2]), "+f"(d[3])
        : "r"(a0), "r"(a1), "r"(a2), "r"(a3), "r"(b0), "r"(b1));
}

__global__ void prep_weights(const float* __restrict__ Wqkv, const float* __restrict__ Wout) {
    const int idx = blockIdx.x * 256 + threadIdx.x;     // 8192 frags
    if (idx >= 8192) return;
    const int lane = idx & 31;
    const int ks   = (idx >> 5) & 7;
    const int wrb  = (idx >> 8) & 3;
    const int ch   = idx >> 10;
    const int g = lane >> 2, t4 = lane & 3;
    const int e0 = ch * 64 + wrb * 16 + g;
    const float* W0 = (ch < 6) ? (Wqkv + (size_t)e0 * CDIM) : (Wout + (size_t)(e0 - 384) * CDIM);
    const float* W8 = W0 + 8 * CDIM;
    const int c0 = ks * 16;
    int cs0, cs1, cs2, cs3;
    if (ch < 6) { cs0 = c0 + t4;     cs1 = c0 + t4 + 4;     cs2 = c0 + 8 + t4;      cs3 = c0 + 12 + t4; }
    else        { cs0 = c0 + t4 * 2; cs1 = c0 + t4 * 2 + 1; cs2 = c0 + t4 * 2 + 8;  cs3 = c0 + t4 * 2 + 9; }
    uint4 h, l;
    split2(W0[cs0], W0[cs1], h.x, l.x);
    split2(W8[cs0], W8[cs1], h.y, l.y);
    split2(W0[cs2], W0[cs3], h.z, l.z);
    split2(W8[cs2], W8[cs3], h.w, l.w);
    gWh[idx] = h;
    gWl[idx] = l;
}

// One 64(e) x 64(t) x 128(c) projection GEMM warp-tile.
__device__ __forceinline__ void gemm_chunk(int ch, int wrb, int nhalf, int lane,
                                           const uint2* __restrict__ bfh,
                                           const uint2* __restrict__ bfl,
                                           float (&d)[4][4])
{
    const uint4* ph = gWh + ((ch * 4 + wrb) * 8) * 32 + lane;
    const uint4* pl = gWl + ((ch * 4 + wrb) * 8) * 32 + lane;
    #pragma unroll
    for (int nt = 0; nt < 4; ++nt)
        #pragma unroll
        for (int j = 0; j < 4; ++j) d[nt][j] = 0.f;

    #pragma unroll
    for (int ks = 0; ks < 8; ++ks) {
        const uint4 ah = __ldg(ph + ks * 32);
        const uint4 al = __ldg(pl + ks * 32);
        #pragma unroll
        for (int nt = 0; nt < 4; ++nt) {
            const int cell = ((nhalf * 4 + nt) * 8 + ks) * 32 + lane;
            const uint2 bh = bfh[cell];
            const uint2 bl = bfl[cell];
            mma_bf16(d[nt], ah.x, ah.y, ah.z, ah.w, bh.x, bh.y);
            mma_bf16(d[nt], ah.x, ah.y, ah.z, ah.w, bl.x, bl.y);
            mma_bf16(d[nt], al.x, al.y, al.z, al.w, bh.x, bh.y);
        }
    }
}

__global__ __launch_bounds__(512, 1)
void lwa3d_mma(const float* __restrict__ x, const float* __restrict__ bout,
               float* __restrict__ out)
{
    extern __shared__ char smc[];
    float* qT  = reinterpret_cast<float*>(smc + O_QT);    // [64 tok][132] (Q pre-scaled)
    float* kT  = reinterpret_cast<float*>(smc + O_KT);    // [64 tok][132]
    float* vcm = reinterpret_cast<float*>(smc + O_VCM);   // [128 ch][68]
    float* pT0 = reinterpret_cast<float*>(smc + O_PT);    // [2 heads][64 q][68] fp32
    float* ps  = reinterpret_cast<float*>(smc + O_PS);    // [2 heads][2][64]
    float* xs  = reinterpret_cast<float*>(smc + O_QT);    // gather scratch (alias)
    uint2* bfh = reinterpret_cast<uint2*>(smc + O_BH);    // [tb8][ks8][lane32]
    uint2* bfl = reinterpret_cast<uint2*>(smc + O_BL);

    const int tid  = threadIdx.x;
    const int wid  = tid >> 5;
    const int lane = tid & 31;
    const int g    = lane >> 2;
    const int t4   = lane & 3;
    const int n = blockIdx.x;
    const int b = blockIdx.y;
    const float scale = 0.08838834764831845f;   // 128^-0.5

    // ---------- gather x window into xs [128c][64t] ----------
    {
        const int ndi = n / 144, nhi = (n / 12) % 12, nwi = n % 12;
        const float* xb = x + (size_t)b * CDIM * SDIM;
        const int sbase = ((ndi * 4) * 48 + nhi * 4) * 48 + nwi * 4;
        for (int i = tid; i < CDIM * 16; i += 512) {
            const int c = i >> 4;
            const int gg = i & 15;
            const int s0 = sbase + ((gg >> 2) * 48 + (gg & 3)) * 48;
            *reinterpret_cast<float4*>(xs + c * XP + gg * 4) =
                *reinterpret_cast<const float4*>(xb + (size_t)c * SDIM + s0);
        }
    }
    __syncthreads();

    // ---------- build bf16 hi/lo B fragments from xs ----------
    // cell(tb,ks,lane): token t = tb*8+g, b0 = {x[ks*16+t4][t], x[ks*16+t4+4][t]},
    //                   b1 = {x[ks*16+8+t4][t], x[ks*16+12+t4][t]}
    for (int cell = tid; cell < 2048; cell += 512) {
        const int l2 = cell & 31;
        const int ks = (cell >> 5) & 7;
        const int tb = cell >> 8;
        const int t  = tb * 8 + (l2 >> 2);
        const int c0 = ks * 16 + (l2 & 3);
        uint32_t h0, l0, h1, l1;
        split2(xs[c0 * XP + t], xs[(c0 + 4) * XP + t], h0, l0);
        split2(xs[(c0 + 8) * XP + t], xs[(c0 + 12) * XP + t], h1, l1);
        bfh[cell] = make_uint2(h0, h1);
        bfl[cell] = make_uint2(l0, l1);
    }
    __syncthreads();

    // ---------- QKV = Wqkv @ x : 48 warp-tasks, 3 per warp ----------
    #pragma unroll 1
    for (int i = 0; i < 3; ++i) {
        const int task  = wid * 3 + i;
        const int ch    = task >> 3;
        const int wrb   = (task >> 1) & 3;
        const int nhalf = task & 1;
        float d[4][4];
        gemm_chunk(ch, wrb, nhalf, lane, bfh, bfl, d);
        const int e0 = (ch & 1) * 64 + wrb * 16 + g;   // channel within section
        const int t0 = nhalf * 32 + t4 * 2;
        if (ch < 2) {            // Q: pre-scaled token-major
            #pragma unroll
            for (int nt = 0; nt < 4; ++nt) {
                const int t = t0 + nt * 8;
                qT[t * QTP + e0]           = d[nt][0] * scale;
                qT[(t + 1) * QTP + e0]     = d[nt][1] * scale;
                qT[t * QTP + e0 + 8]       = d[nt][2] * scale;
                qT[(t + 1) * QTP + e0 + 8] = d[nt][3] * scale;
            }
        } else if (ch < 4) {     // K: token-major
            #pragma unroll
            for (int nt = 0; nt < 4; ++nt) {
                const int t = t0 + nt * 8;
                kT[t * QTP + e0]           = d[nt][0];
                kT[(t + 1) * QTP + e0]     = d[nt][1];
                kT[t * QTP + e0 + 8]       = d[nt][2];
                kT[(t + 1) * QTP + e0 + 8] = d[nt][3];
            }
        } else {                 // V: channel-major
            float* v0 = vcm + e0 * VP + t0;
            float* v1 = v0 + 8 * VP;
            #pragma unroll
            for (int nt = 0; nt < 4; ++nt) {
                *reinterpret_cast<float2*>(v0 + nt * 8) = make_float2(d[nt][0], d[nt][1]);
                *reinterpret_cast<float2*>(v1 + nt * 8) = make_float2(d[nt][2], d[nt][3]);
            }
        }
    }
    __syncthreads();

    // ---------- MMA attention: 2 heads in flight ----------
    const int hsel = wid >> 3;          // which of the 2 concurrent heads
    const int sub  = wid & 7;
    const int mb  = sub >> 1;           // QK: 16q row-block
    const int nh  = sub & 1;            // QK: 32k col-half
    const int mbp = sub & 3;            // PV: 16q row-block
    const int nhd = sub >> 2;           // PV: 8hd col-half
    float* pT  = pT0 + hsel * 64 * PP;
    float* psh = ps + hsel * 128;
    uint32_t* bhw = reinterpret_cast<uint32_t*>(bfh);
    uint32_t* blw = reinterpret_cast<uint32_t*>(bfl);

    #pragma unroll 1
    for (int hh = 0; hh < 4; ++hh) {
        const int h = hh * 2 + hsel;

        // ---- S = Q K^T (scaled): K=16, one k-step, 3-term bf16 ----
        float d[4][4];
        #pragma unroll
        for (int nt = 0; nt < 4; ++nt)
            #pragma unroll
            for (int j = 0; j < 4; ++j) d[nt][j] = 0.f;

        {
            const float* q0 = qT + (mb * 16 + g) * QTP + h * 16 + t4;
            const float* q8 = q0 + 8 * QTP;
            uint32_t ah[4], al[4];
            split2(q0[0], q0[4],  ah[0], al[0]);
            split2(q8[0], q8[4],  ah[1], al[1]);
            split2(q0[8], q0[12], ah[2], al[2]);
            split2(q8[8], q8[12], ah[3], al[3]);
            #pragma unroll
            for (int nt = 0; nt < 4; ++nt) {
                const float* k0 = kT + (nh * 32 + nt * 8 + g) * QTP + h * 16 + t4;
                uint32_t bh0, bl0, bh1, bl1;
                split2(k0[0], k0[4],  bh0, bl0);
                split2(k0[8], k0[12], bh1, bl1);
                mma_bf16(d[nt], ah[0], ah[1], ah[2], ah[3], bh0, bh1);
                mma_bf16(d[nt], ah[0], ah[1], ah[2], ah[3], bl0, bl1);
                mma_bf16(d[nt], al[0], al[1], al[2], al[3], bh0, bh1);
            }
        }

        // ---- exp (unnormalized P) + row sums ----
        float e[4][4];
        float s0 = 0.f, s1 = 0.f;
        #pragma unroll
        for (int nt = 0; nt < 4; ++nt) {
            e[nt][0] = __expf(d[nt][0]);
            e[nt][1] = __expf(d[nt][1]);
            e[nt][2] = __expf(d[nt][2]);
            e[nt][3] = __expf(d[nt][3]);
            s0 += e[nt][0] + e[nt][1];
            s1 += e[nt][2] + e[nt][3];
        }
        s0 += __shfl_xor_sync(0xFFFFFFFF, s0, 1);
        s0 += __shfl_xor_sync(0xFFFFFFFF, s0, 2);
        s1 += __shfl_xor_sync(0xFFFFFFFF, s1, 1);
        s1 += __shfl_xor_sync(0xFFFFFFFF, s1, 2);
        if (t4 == 0) {
            psh[nh * 64 + mb * 16 + g]     = s0;
            psh[nh * 64 + mb * 16 + g + 8] = s1;
        }

        // ---- write P (fp32) to pT[q][kt] ----
        {
            const int q0r = mb * 16 + g;
            const int kt0 = nh * 32 + t4 * 2;
            #pragma unroll
            for (int nt = 0; nt < 4; ++nt) {
                const int kt = kt0 + nt * 8;
                *reinterpret_cast<float2*>(pT + q0r * PP + kt)       = make_float2(e[nt][0], e[nt][1]);
                *reinterpret_cast<float2*>(pT + (q0r + 8) * PP + kt) = make_float2(e[nt][2], e[nt][3]);
            }
        }
        __syncthreads();

        // ---- O = P V : K=64, 4 k-steps of 16, two accum chains ----
        float oa[4] = {0.f, 0.f, 0.f, 0.f};
        float ob[4] = {0.f, 0.f, 0.f, 0.f};
        #pragma unroll
        for (int ks = 0; ks < 4; ++ks) {
            const int kt0 = ks * 16;
            const float* p0 = pT + (mbp * 16 + g) * PP + kt0 + t4;
            const float* p8 = p0 + 8 * PP;
            uint32_t ah0, al0, ah1, al1, ah2, al2, ah3, al3;
            split2(p0[0], p0[4],  ah0, al0);
            split2(p8[0], p8[4],  ah1, al1);
            split2(p0[8], p0[12], ah2, al2);
            split2(p8[8], p8[12], ah3, al3);
            const float* vp = vcm + (h * 16 + nhd * 8 + g) * VP + kt0 + t4;
            uint32_t vh0, vl0, vh1, vl1;
            split2(vp[0], vp[4],  vh0, vl0);
            split2(vp[8], vp[12], vh1, vl1);
            float* acc = (ks & 1) ? ob : oa;
            mma_bf16(acc, ah0, ah1, ah2, ah3, vh0, vh1);
            mma_bf16(acc, ah0, ah1, ah2, ah3, vl0, vl1);
            mma_bf16(acc, al0, al1, al2, al3, vh0, vh1);
        }
        #pragma unroll
        for (int j = 0; j < 4; ++j) oa[j] += ob[j];

        // ---- normalize + store as out-proj B fragments ----
        // thread holds O[q][c],O[q][c+1] (c = h*16+nhd*8+2t4) and rows q+8.
        {
            const int q0r = mbp * 16 + g;
            const float r0 = 1.f / (psh[q0r] + psh[64 + q0r]);
            const float r1 = 1.f / (psh[q0r + 8] + psh[64 + q0r + 8]);
            uint32_t h0, l0, h1, l1;
            split2(oa[0] * r0, oa[1] * r0, h0, l0);
            split2(oa[2] * r1, oa[3] * r1, h1, l1);
            const int cellA = ((mbp * 2) * 8 + h) * 32 + g * 4 + t4;      // token q0r
            const int cellB = ((mbp * 2 + 1) * 8 + h) * 32 + g * 4 + t4;  // token q0r+8
            bhw[cellA * 2 + nhd] = h0;
            blw[cellA * 2 + nhd] = l0;
            bhw[cellB * 2 + nhd] = h1;
            blw[cellB * 2 + nhd] = l1;
        }
        __syncthreads();   // protect pT/ps before next head pair
    }

    // ---------- out = Wout @ ao + bout : 16 warp-tasks, 1 per warp ----------
    {
        const int ch    = 6 + (wid >> 3);
        const int wrb   = (wid >> 1) & 3;
        const int nhalf = wid & 1;
        float d[4][4];
        gemm_chunk(ch, wrb, nhalf, lane, bfh, bfl, d);
        const int e0 = (ch - 6) * 64 + wrb * 16 + g;
        const float bb0 = __ldg(bout + e0);
        const float bb1 = __ldg(bout + e0 + 8);
        float* o0 = out + (size_t)b * CDIM * SDIM + (size_t)e0 * SDIM + n * 64 + nhalf * 32 + t4 * 2;
        float* o1 = o0 + (size_t)8 * SDIM;
        #pragma unroll
        for (int nt = 0; nt < 4; ++nt) {
            *reinterpret_cast<float2*>(o0 + nt * 8) = make_float2(d[nt][0] + bb0, d[nt][1] + bb0);
            *reinterpret_cast<float2*>(o1 + nt * 8) = make_float2(d[nt][2] + bb1, d[nt][3] + bb1);
        }
    }
}

extern "C" void kernel_launch(void* const* d_in, const int* in_sizes, int n_in,
                              void* d_out, int out_size)
{
    (void)in_sizes; (void)n_in; (void)out_size;
    const float* x    = (const float*)d_in[0];
    const float* Wqkv = (const float*)d_in[1];
    const float* Wout = (const float*)d_in[2];
    const float* bout = (const float*)d_in[3];
    float* out = (float*)d_out;

    prep_weights<<<32, 256>>>(Wqkv, Wout);

    cudaFuncSetAttribute(lwa3d_mma, cudaFuncAttributeMaxDynamicSharedMemorySize, SMEM_BYTES);
    dim3 grid(NWIN, 2);
    lwa3d_mma<<<grid, 512, SMEM_BYTES>>>(x, bout, out);
}